// round 11
// baseline (speedup 1.0000x reference)
#include <cuda_runtime.h>
#include <math.h>

typedef unsigned long long u64;

#define BATCH 64
#define H 224
#define W 224
#define NPAIR 192            // BATCH*3
#define ACC_STRIDE 132       // 128 hist bins + nc/pc/ma + pad
#define ACC_INTS (5 * NPAIR * ACC_STRIDE)

// Staged segments (k=11,9,7,5): block = (pair, 8-row chunk)
#define NRC11 3              // ceil(21/8)
#define NRC9  4              // ceil(25/8)
#define NRC7  4              // 32/8
#define NRC5  6              // ceil(45/8)
#define B11E (NPAIR * NRC11)                 // 576
#define B9E  (B11E + NPAIR * NRC9)           // 1344
#define B7E  (B9E  + NPAIR * NRC7)           // 2112
#define B5E  (B7E  + NPAIR * NRC5)           // 3264
// k=3: per-thread LUT path, 22 chunks
#define C3   22
#define TOTAL_BLOCKS (B5E + C3 * NPAIR)      // 7488

// Device scratch (no allocation allowed)
__device__ float g_planes[3][BATCH * H * W];
__device__ float g_feat[BATCH * 75];
__device__ int   g_acc[ACC_INTS];
__device__ unsigned short g_lut3[512];   // k=3 mask -> {nc | maxarea<<8}

// Column masks for K=11 (stride 11, 128-bit mask in 2x u64)
constexpr u64 colmask_lo(int c) {
    u64 m = 0;
    for (int r = 0; r < 11; r++) { int p = r * 11 + c; if (p < 64) m |= 1ull << p; }
    return m;
}
constexpr u64 colmask_hi(int c) {
    u64 m = 0;
    for (int r = 0; r < 11; r++) { int p = r * 11 + c; if (p >= 64) m |= 1ull << (p - 64); }
    return m;
}
constexpr u64 NOTC0_LO  = ~colmask_lo(0);
constexpr u64 NOTC0_HI  = ~colmask_hi(0);
constexpr u64 NOTC10_LO = ~colmask_lo(10);
constexpr u64 NOTC10_HI = ~colmask_hi(10);

// ---------------------------------------------------------------------------
// Kernel 1: NHWC -> channel planes (float4) + zero accumulators + build k3 LUT
// ---------------------------------------------------------------------------
__global__ void transpose_kernel(const float4* __restrict__ in4) {
    int t = blockIdx.x * blockDim.x + threadIdx.x;
    if (t < ACC_INTS) g_acc[t] = 0;
    if (t < 512) {
        int nc = 0, best = 0, rem = t;
        while (rem) {
            int cur = rem & (-rem);
            while (true) {
                int g = cur | ((cur << 1) & 0x1B6) | ((cur >> 1) & 0x0DB)
                            | (cur << 3) | (cur >> 3);
                g &= rem;
                if (g == cur) break;
                cur = g;
            }
            nc++;
            int a = __popc(cur);
            if (a > best) best = a;
            rem ^= cur;
        }
        g_lut3[t] = (unsigned short)(nc | (best << 8));
    }
    const int NT = BATCH * H * W / 4;   // 802816
    if (t >= NT) return;
    float4 f0 = in4[3 * t + 0];
    float4 f1 = in4[3 * t + 1];
    float4 f2 = in4[3 * t + 2];
    ((float4*)g_planes[0])[t] = make_float4(f0.x, f0.w, f1.z, f2.y);
    ((float4*)g_planes[1])[t] = make_float4(f0.y, f1.x, f1.w, f2.z);
    ((float4*)g_planes[2])[t] = make_float4(f0.z, f1.y, f2.x, f2.w);
}

// 128-bit neighbor expansion (stride 11)
template <int K>
__device__ __forceinline__ void expand128(u64 clo, u64 chi, u64& glo, u64& ghi) {
    u64 l1lo = clo << 1;
    u64 l1hi = (chi << 1) | (clo >> 63);
    u64 r1lo = (clo >> 1) | (chi << 63);
    u64 r1hi = chi >> 1;
    if (K == 11) {
        l1lo &= NOTC0_LO;  l1hi &= NOTC0_HI;
        r1lo &= NOTC10_LO; r1hi &= NOTC10_HI;
    }
    u64 uplo = clo << 11;
    u64 uphi = (chi << 11) | (clo >> 53);
    u64 dnlo = (clo >> 11) | (chi << 53);
    u64 dnhi = chi >> 11;
    glo = l1lo | r1lo | uplo | dnlo;
    ghi = l1hi | r1hi | uphi | dnhi;
}

// ---------------------------------------------------------------------------
// Staged body: k=5,7,9,11. Warp owns one patch row; rows staged through a
// per-warp double-buffered smem strip (coalesced LDG, conflict-free LDS).
// ---------------------------------------------------------------------------
template <int K, int NRC, int SEG>
__device__ __forceinline__ void staged_body(int rel, int* sh, float (*sbuf)[352]) {
    constexpr int ROWS = (H + K - 1) / K;
    constexpr int COLS = (W + K - 1) / K;
    constexpr int PADT = (ROWS * K - H) / 2;
    constexpr int PADL = (COLS * K - W) / 2;
    constexpr int KK   = K * K;
    constexpr int STRIDE = (K <= 7) ? 8 : 11;
    constexpr bool WIDE  = (K > 7);
    constexpr int PASSES = (COLS + 31) / 32;
    constexpr int PTH = (K == 5) ? 15 : (K == 7) ? 30 : (K == 9) ? 49 : 72;

    const int pair  = rel / NRC;
    const int chunk = rel - pair * NRC;
    const int b  = pair / 3;
    const int ch = pair % 3;
    const float* __restrict__ plane = g_planes[ch] + b * (H * W);

    const int tid  = threadIdx.x;
    const int warp = tid >> 5;
    const int lane = tid & 31;

    for (int q = tid; q < ACC_STRIDE - 1; q += 256) sh[q] = 0;
    __syncthreads();

    const int i = chunk * 8 + warp;   // patch row
    int t_nc = 0, t_pc = 0, t_ma = 0;

    if (i < ROWS) {
        const int r0 = i * K - PADT;
        #pragma unroll
        for (int pass = 0; pass < PASSES; pass++) {
            const int jbase = pass * 32;
            const int j     = jbase + lane;
            const bool valid = (j < COLS);
            const unsigned vmask = __ballot_sync(0xffffffffu, valid);

            const float center = valid
                ? __ldg(plane + (r0 + K / 2) * W + (j * K - PADL + K / 2)) : 0.0f;
            const int col0 = jbase * K - PADL;

            u64 mlo = 0, mhi = 0;
            #pragma unroll
            for (int dy = 0; dy < K; dy++) {
                float* buf = sbuf[dy & 1];
                const int r = r0 + dy;
                if ((unsigned)r < (unsigned)H) {
                    const float* rowp = plane + r * W;
                    #pragma unroll
                    for (int q = 0; q < K; q++) {
                        int idx = col0 + lane + 32 * q;
                        buf[lane + 32 * q] =
                            ((unsigned)idx < (unsigned)W) ? __ldg(rowp + idx) : 0.0f;
                    }
                } else {
                    #pragma unroll
                    for (int q = 0; q < K; q++) buf[lane + 32 * q] = 0.0f;
                }
                __syncwarp();
                if (valid) {
                    unsigned m = 0;
                    const float* pp = buf + lane * K;
                    #pragma unroll
                    for (int dx = 0; dx < K; dx++)
                        if (fabsf(pp[dx] - center) <= (float)K) m |= (1u << dx);
                    const int p = dy * STRIDE;
                    if (p < 64) {
                        mlo |= (u64)m << p;
                        if (p + K > 64) mhi |= (u64)m >> (64 - p);
                    } else {
                        mhi |= (u64)m << (p - 64);
                    }
                }
            }

            if (valid) {
                int ones, nc, best;
                if (!WIDE) {
                    ones = __popcll(mlo);
                    best = KK - ones;
                    const u64 m = mlo;
                    u64 neigh = (m << 1) | (m >> 1) | (m << 8) | (m >> 8);
                    u64 iso = m & ~neigh;
                    nc = __popcll(iso);
                    u64 rem = m ^ iso;
                    while (rem) {
                        u64 cur = rem & (0ull - rem);
                        while (true) {
                            u64 g1 = (cur | (cur << 1) | (cur >> 1) | (cur << 8) | (cur >> 8)) & rem;
                            u64 g2 = (g1 | (g1 << 1) | (g1 >> 1) | (g1 << 8) | (g1 >> 8)) & rem;
                            if (g2 == cur) break;
                            cur = g2;
                        }
                        int a = __popcll(cur);
                        if (a > best) best = a;
                        rem ^= cur;
                        nc++;
                    }
                } else {
                    ones = __popcll(mlo) + __popcll(mhi);
                    best = KK - ones;
                    u64 nlo, nhi;
                    expand128<K>(mlo, mhi, nlo, nhi);
                    u64 isolo = mlo & ~nlo, isohi = mhi & ~nhi;
                    nc = __popcll(isolo) + __popcll(isohi);
                    u64 rlo = mlo ^ isolo, rhi = mhi ^ isohi;
                    while (rlo | rhi) {
                        u64 clo, chi;
                        if (rlo) { clo = rlo & (0ull - rlo); chi = 0; }
                        else     { clo = 0; chi = rhi & (0ull - rhi); }
                        while (true) {
                            u64 elo, ehi, g1lo, g1hi, g2lo, g2hi;
                            expand128<K>(clo, chi, elo, ehi);
                            g1lo = (clo | elo) & rlo;
                            g1hi = (chi | ehi) & rhi;
                            expand128<K>(g1lo, g1hi, elo, ehi);
                            g2lo = (g1lo | elo) & rlo;
                            g2hi = (g1hi | ehi) & rhi;
                            if (g2lo == clo && g2hi == chi) break;
                            clo = g2lo; chi = g2hi;
                        }
                        int a = __popcll(clo) + __popcll(chi);
                        if (a > best) best = a;
                        rlo ^= clo; rhi ^= chi;
                        nc++;
                    }
                }

                unsigned peers = __match_any_sync(vmask, ones);
                if (lane == (__ffs(peers) - 1))
                    atomicAdd(&sh[ones], __popc(peers));

                t_nc += nc;
                t_pc += (ones >= PTH) ? 1 : 0;
                t_ma += best;
            }
        }
    }

    t_nc = __reduce_add_sync(0xffffffffu, t_nc);
    t_pc = __reduce_add_sync(0xffffffffu, t_pc);
    t_ma = __reduce_add_sync(0xffffffffu, t_ma);
    if (lane == 0 && (t_nc | t_pc | t_ma)) {
        atomicAdd(&sh[128], t_nc);
        atomicAdd(&sh[129], t_pc);
        atomicAdd(&sh[130], t_ma);
    }
    __syncthreads();

    int* dst = g_acc + (SEG * NPAIR + pair) * ACC_STRIDE;
    for (int q = tid; q < ACC_STRIDE - 1; q += 256) {
        int v = sh[q];
        if (v) atomicAdd(&dst[q], v);
    }
}

// ---------------------------------------------------------------------------
// k=3 body: per-thread path with global CC LUT (measured-best R10 path)
// ---------------------------------------------------------------------------
__device__ __forceinline__ void k3_body(int rel, int* sh) {
    constexpr int COLS = 75, ROWS = 75, P = ROWS * COLS;   // 5625
    const int chunk = rel / NPAIR;
    const int pair  = rel % NPAIR;
    const int b  = pair / 3;
    const int ch = pair % 3;
    const float* __restrict__ plane = g_planes[ch] + b * (H * W);

    for (int q = threadIdx.x; q < ACC_STRIDE - 1; q += 256) sh[q] = 0;
    __syncthreads();

    int t_nc = 0, t_pc = 0, t_ma = 0;

    for (int pidx = chunk * 256 + threadIdx.x; pidx < P; pidx += C3 * 256) {
        const int i  = pidx / COLS;
        const int j  = pidx % COLS;
        const int r0 = i * 3;
        const int c0 = j * 3;

        const float center = __ldg(plane + (r0 + 1) * W + (c0 + 1));
        const bool interior = (r0 + 3 <= H) & (c0 + 3 <= W);

        int m9 = 0;
        if (interior) {
            const float* base = plane + r0 * W + c0;
            #pragma unroll
            for (int dy = 0; dy < 3; dy++)
                #pragma unroll
                for (int dx = 0; dx < 3; dx++) {
                    float v = __ldg(base + dy * W + dx);
                    if (fabsf(v - center) <= 3.0f) m9 |= 1 << (3 * dy + dx);
                }
        } else {
            #pragma unroll
            for (int dy = 0; dy < 3; dy++) {
                const int r = r0 + dy;
                #pragma unroll
                for (int dx = 0; dx < 3; dx++) {
                    const int c = c0 + dx;
                    float v = (r < H && c < W) ? __ldg(plane + r * W + c) : 0.0f;
                    if (fabsf(v - center) <= 3.0f) m9 |= 1 << (3 * dy + dx);
                }
            }
        }

        const int ones = __popc(m9);
        unsigned val = __ldg(&g_lut3[m9]);
        int nc = val & 0xFF;
        int best = val >> 8;
        int bg = 9 - ones;
        if (bg > best) best = bg;

        {
            unsigned act   = __activemask();
            unsigned peers = __match_any_sync(act, ones);
            if ((threadIdx.x & 31) == (__ffs(peers) - 1))
                atomicAdd(&sh[ones], __popc(peers));
        }
        t_nc += nc;
        t_pc += (ones >= 6) ? 1 : 0;
        t_ma += best;
    }

    atomicAdd(&sh[128], t_nc);
    atomicAdd(&sh[129], t_pc);
    atomicAdd(&sh[130], t_ma);
    __syncthreads();

    int* dst = g_acc + (4 * NPAIR + pair) * ACC_STRIDE;
    for (int q = threadIdx.x; q < ACC_STRIDE - 1; q += 256) {
        int v = sh[q];
        if (v) atomicAdd(&dst[q], v);
    }
}

__global__ __launch_bounds__(256) void patch_all_kernel() {
    __shared__ int sh[ACC_STRIDE - 1];
    __shared__ float sbuf[8][2][352];   // per-warp double-buffered strip
    const int blk = blockIdx.x;
    const int warp = threadIdx.x >> 5;
    if (blk < B11E)      staged_body<11, NRC11, 0>(blk, sh, sbuf[warp]);
    else if (blk < B9E)  staged_body<9,  NRC9,  1>(blk - B11E, sh, sbuf[warp]);
    else if (blk < B7E)  staged_body<7,  NRC7,  2>(blk - B9E,  sh, sbuf[warp]);
    else if (blk < B5E)  staged_body<5,  NRC5,  3>(blk - B7E,  sh, sbuf[warp]);
    else                 k3_body(blk - B5E, sh);
}

// ---------------------------------------------------------------------------
// Kernel 3: finalize metrics -> (B,5,5,3) feature map
// ---------------------------------------------------------------------------
__global__ void finalize_kernel() {
    int tid = blockIdx.x * blockDim.x + threadIdx.x;
    if (tid >= 5 * NPAIR) return;
    const int seg  = tid / NPAIR;
    const int pair = tid % NPAIR;
    const int b  = pair / 3;
    const int ch = pair % 3;

    const int K  = 11 - 2 * seg;          // seg order: 11,9,7,5,3
    const int KK = K * K;
    const int ROWS = (H + K - 1) / K;
    const int COLS = (W + K - 1) / K;
    const int P    = ROWS * COLS;

    const int* acc = g_acc + (seg * NPAIR + pair) * ACC_STRIDE;
    const float fP = (float)P;
    float fd = 0.0f, m = 0.0f, m2 = 0.0f;
    for (int q = 0; q < KK; q++) {
        float p = (float)acc[q] / fP;
        float n = (float)(q + 1);
        fd += p / n;
        m  += p * n;
        m2 += p * p * n;
    }
    float lac = (m2 - m * m) / (m * m);
    int acn  = acc[128] / P;
    int acp  = acc[129] / P;
    int acma = acc[130] / P;

    const int kidx = (K - 3) / 2;
    const int o = ((b * 5) * 5 + kidx) * 3 + ch;
    g_feat[o + 0 * 15] = (float)acn;
    g_feat[o + 1 * 15] = (float)acp;
    g_feat[o + 2 * 15] = (float)acma;
    g_feat[o + 3 * 15] = lac;
    g_feat[o + 4 * 15] = fd;
}

// ---------------------------------------------------------------------------
// Kernel 4: bilinear resize via smem pre-lerped rows, float4 LDS
// ---------------------------------------------------------------------------
#define RCHUNK 28
#define YBLKS (H / RCHUNK)   // 8
#define WC (W * 3)           // 672

__global__ __launch_bounds__(256) void resize_kernel(float* __restrict__ out) {
    __shared__ float feat[75];
    __shared__ __align__(16) float hrow[5 * WC];
    __shared__ float s_fy[RCHUNK];
    __shared__ int   s_y0[RCHUNK], s_y1[RCHUNK];

    const int b   = blockIdx.x / YBLKS;
    const int yc  = blockIdx.x % YBLKS;
    const int tid = threadIdx.x;

    if (tid < 75) feat[tid] = g_feat[b * 75 + tid];
    if (tid >= 96 && tid < 96 + RCHUNK) {
        int y = yc * RCHUNK + (tid - 96);
        float cy = ((float)y + 0.5f) * (5.0f / 224.0f) - 0.5f;
        float fl = floorf(cy);
        int y0 = (int)fl;
        float fy = cy - fl;
        int y0c = max(y0, 0), y1c = min(y0 + 1, 4);
        s_fy[tid - 96] = fy;
        s_y0[tid - 96] = y0c * WC;
        s_y1[tid - 96] = y1c * WC;
    }
    __syncthreads();

    for (int i = tid; i < 5 * WC; i += 256) {
        int r  = i / WC;
        int xc = i - r * WC;
        int x  = xc / 3;
        int ch = xc - x * 3;
        float cx = ((float)x + 0.5f) * (5.0f / 224.0f) - 0.5f;
        float fl = floorf(cx);
        int x0 = (int)fl;
        float fx = cx - fl;
        int x0c = max(x0, 0), x1c = min(x0 + 1, 4);
        float a  = feat[(r * 5 + x0c) * 3 + ch];
        float bb = feat[(r * 5 + x1c) * 3 + ch];
        hrow[i] = a + fx * (bb - a);
    }
    __syncthreads();

    float4* o4 = (float4*)(out + b * (H * WC) + yc * (RCHUNK * WC));
    const int N4 = RCHUNK * WC / 4;
    for (int i = tid; i < N4; i += 256) {
        int yl = i / (WC / 4);
        int x4 = i - yl * (WC / 4);
        const float4 a  = *(const float4*)&hrow[s_y0[yl] + 4 * x4];
        const float4 bb = *(const float4*)&hrow[s_y1[yl] + 4 * x4];
        const float fy = s_fy[yl];
        float4 v;
        v.x = a.x + fy * (bb.x - a.x);
        v.y = a.y + fy * (bb.y - a.y);
        v.z = a.z + fy * (bb.z - a.z);
        v.w = a.w + fy * (bb.w - a.w);
        o4[i] = v;
    }
}

// ---------------------------------------------------------------------------
extern "C" void kernel_launch(void* const* d_in, const int* in_sizes, int n_in,
                              void* d_out, int out_size) {
    const float4* in4 = (const float4*)d_in[0];
    float* out = (float*)d_out;

    const int NT = BATCH * H * W / 4;   // 802816
    transpose_kernel<<<NT / 256, 256>>>(in4);
    patch_all_kernel<<<TOTAL_BLOCKS, 256>>>();
    finalize_kernel<<<(5 * NPAIR + 255) / 256, 256>>>();
    resize_kernel<<<BATCH * YBLKS, 256>>>(out);
}